// round 9
// baseline (speedup 1.0000x reference)
#include <cuda_runtime.h>

// Problem constants
#define QQ 30
#define KK 1024
#define DD 128
#define BB 16
#define TT 2048
#define NTOK (BB*TT)          // 32768 tokens
#define OUT_ELEMS (NTOK*DD)   // 4194304 quantized elements

// Tiling
#define TM 128                // tokens per CTA
#define KC 128                // codes per chunk
#define NCH (KK/KC)           // 8 chunks
#define NT 256                // threads per CTA

// Scratch (no cudaMalloc allowed): transposed codebooks [q][d][k] + code norms
__device__ float g_ct[(size_t)QQ*DD*KK];   // 15.7 MB
__device__ float g_cn[QQ*KK];              // 120 KB

// ---------------------------------------------------------------------------
// Packed fp32x2 helpers (Blackwell FFMA2 path). Per-lane IEEE fp32 rn:
// bitwise identical to two scalar __fmaf_rn chains -> decisions unchanged.
// ---------------------------------------------------------------------------
__device__ __forceinline__ unsigned long long pack2(float lo, float hi)
{
    unsigned long long r;
    asm("mov.b64 %0, {%1, %2};" : "=l"(r) : "f"(lo), "f"(hi));
    return r;
}
__device__ __forceinline__ void unpack2(float& lo, float& hi, unsigned long long v)
{
    asm("mov.b64 {%0, %1}, %2;" : "=f"(lo), "=f"(hi) : "l"(v));
}
__device__ __forceinline__ void fma2(unsigned long long& acc,
                                     unsigned long long a, unsigned long long b)
{
    asm("fma.rn.f32x2 %0, %1, %2, %0;" : "+l"(acc) : "l"(a), "l"(b));
}

// ---------------------------------------------------------------------------
// Reference-exact square-sum reduce (DO NOT TOUCH -- validated bit-exact):
// two 4-lane shards, lane l of a0 += x^2[8j+l], a1 += x^2[8j+4+l], j asc;
// combine lanewise then sequential left-assoc extraction ((v0+v1)+v2)+v3.
// ---------------------------------------------------------------------------
#define RED_ACC(a0, a1, v0, v1, v2, v3, v4, v5, v6, v7)                  \
    do {                                                                 \
        a0[0] = __fmaf_rn((v0), (v0), a0[0]);                            \
        a0[1] = __fmaf_rn((v1), (v1), a0[1]);                            \
        a0[2] = __fmaf_rn((v2), (v2), a0[2]);                            \
        a0[3] = __fmaf_rn((v3), (v3), a0[3]);                            \
        a1[0] = __fmaf_rn((v4), (v4), a1[0]);                            \
        a1[1] = __fmaf_rn((v5), (v5), a1[1]);                            \
        a1[2] = __fmaf_rn((v6), (v6), a1[2]);                            \
        a1[3] = __fmaf_rn((v7), (v7), a1[3]);                            \
    } while (0)

__device__ __forceinline__ float red_combine(const float a0[4], const float a1[4])
{
    float v0 = __fadd_rn(a0[0], a1[0]);
    float v1 = __fadd_rn(a0[1], a1[1]);
    float v2 = __fadd_rn(a0[2], a1[2]);
    float v3 = __fadd_rn(a0[3], a1[3]);
    return __fadd_rn(__fadd_rn(__fadd_rn(v0, v1), v2), v3);
}

// ---------------------------------------------------------------------------
// Prep A: transpose codebooks to [q][d][k]; zero loss slot. Warp per code row.
// ---------------------------------------------------------------------------
__global__ void rvq_prep_kernel(const float* __restrict__ cb,
                                float* __restrict__ out, int write_loss)
{
    if (write_loss && blockIdx.x == 0 && threadIdx.x == 0)
        out[OUT_ELEMS] = 0.0f;

    int gw   = blockIdx.x * 8 + (threadIdx.x >> 5);   // global code row (q*KK+k)
    int lane = threadIdx.x & 31;
    if (gw >= QQ * KK) return;

    int q = gw >> 10;
    int k = gw & (KK - 1);

    float4 v = __ldg(((const float4*)cb) + (size_t)gw * (DD/4) + lane);

    float* base = g_ct + (size_t)q * DD * KK + k;
    int d0 = lane * 4;
    base[(size_t)(d0+0)*KK] = v.x;
    base[(size_t)(d0+1)*KK] = v.y;
    base[(size_t)(d0+2)*KK] = v.z;
    base[(size_t)(d0+3)*KK] = v.w;
}

// ---------------------------------------------------------------------------
// Prep B: ||c||^2 with the validated sharded-vector association.
// ---------------------------------------------------------------------------
__global__ void rvq_norm_kernel(const float* __restrict__ cb)
{
    int gw = blockIdx.x * blockDim.x + threadIdx.x;   // code row (q*KK+k)
    if (gw >= QQ * KK) return;
    const float4* row = ((const float4*)cb) + (size_t)gw * (DD/4);
    float a0[4] = {0.f,0.f,0.f,0.f}, a1[4] = {0.f,0.f,0.f,0.f};
    #pragma unroll
    for (int j = 0; j < 16; j++) {
        float4 A = __ldg(row + 2*j);
        float4 B = __ldg(row + 2*j + 1);
        RED_ACC(a0, a1, A.x, A.y, A.z, A.w, B.x, B.y, B.z, B.w);
    }
    g_cn[gw] = red_combine(a0, a1);
}

// ---------------------------------------------------------------------------
// Main kernel. Identical structure & arithmetic to the passing round; the
// GEMM inner loop now issues packed fma.rn.f32x2 (2 MACs/instr, per-lane
// rounding identical to the scalar chain).
// ---------------------------------------------------------------------------
__global__ __launch_bounds__(NT, 1)
void rvq_kernel(const float* __restrict__ x,
                const float* __restrict__ cb,
                float* __restrict__ out, int write_loss)
{
    extern __shared__ char smraw[];
    float*  rs    = (float*)smraw;                   // residuals [DD][TM]
    float*  cs    = rs + DD*TM;                      // code chunk [DD][KC]
    float*  r2_s  = cs + DD*KC;                      // [TM] ||r||^2 per token
    int*    idx_s = (int*)(r2_s + TM);               // [TM] winner per token
    double* red   = (double*)(idx_s + TM);           // [8] loss partials

    const int tid = threadIdx.x;
    const int tx  = tid & 15;      // code-thread column (16)
    const int ty  = tid >> 4;      // token-thread row   (16)

    const int blk = blockIdx.x;
    const int b   = blk >> 4;            // TT/TM = 16 tiles per batch row
    const int t0  = (blk & 15) * TM;
    const float* xb = x + (size_t)b * DD * TT + t0;

    float4* rs4 = (float4*)rs;
    float4* cs4 = (float4*)cs;

    // Load initial residual r0 = x (transposed into [d][token]); coalesced.
    for (int i = tid; i < DD*TM/4; i += NT) {
        int tok4 = i & 31, d = i >> 5;
        float4 v = __ldg((const float4*)(xb + (size_t)d * TT) + tok4);
        rs4[d * (TM/4) + tok4] = v;
    }
    __syncthreads();

    // Initial r2 with the validated association.
    if (tid < TM) {
        float a0[4] = {0.f,0.f,0.f,0.f}, a1[4] = {0.f,0.f,0.f,0.f};
        #pragma unroll
        for (int j = 0; j < 16; j++) {
            int d = 8*j;
            RED_ACC(a0, a1,
                    rs[(d+0)*TM + tid], rs[(d+1)*TM + tid],
                    rs[(d+2)*TM + tid], rs[(d+3)*TM + tid],
                    rs[(d+4)*TM + tid], rs[(d+5)*TM + tid],
                    rs[(d+6)*TM + tid], rs[(d+7)*TM + tid]);
        }
        r2_s[tid] = red_combine(a0, a1);
    }

    double lossAcc = 0.0;

    for (int q = 0; q < QQ; q++) {
        // Running best per owned token row: key = (sortable bits << 32) | idx
        unsigned long long best[8];
        #pragma unroll
        for (int r = 0; r < 8; r++) best[r] = 0xFFFFFFFFFFFFFFFFull;

        const float* ctq = g_ct + (size_t)q * DD * KK;
        const float* cnq = g_cn + q * KK;

        for (int ch = 0; ch < NCH; ch++) {
            __syncthreads();   // rs/r2 writes (prev) & cs reads (prev chunk) done
            for (int i = tid; i < DD*KC/4; i += NT) {
                int k4 = i & 31, d = i >> 5;
                float4 v = __ldg((const float4*)(ctq + (size_t)d * KK + ch*KC) + k4);
                cs4[d * (KC/4) + k4] = v;
            }
            __syncthreads();

            // 8x8 register tile via packed f32x2: acc2[r][cp] holds columns
            // (2cp, 2cp+1). Each scalar lane's chain: ascending-d single FMA
            // chain -- bitwise identical to the validated scalar version.
            unsigned long long acc2[8][4];
            #pragma unroll
            for (int r = 0; r < 8; r++)
                #pragma unroll
                for (int cp = 0; cp < 4; cp++) acc2[r][cp] = 0ull;

            #pragma unroll 4
            for (int d = 0; d < DD; d++) {
                float4 a0 = rs4[d * (TM/4) + ty*2];
                float4 a1 = rs4[d * (TM/4) + ty*2 + 1];
                float4 b0 = cs4[d * (KC/4) + tx*2];
                float4 b1 = cs4[d * (KC/4) + tx*2 + 1];
                unsigned long long bp[4];
                bp[0] = pack2(b0.x, b0.y);
                bp[1] = pack2(b0.z, b0.w);
                bp[2] = pack2(b1.x, b1.y);
                bp[3] = pack2(b1.z, b1.w);
                float ar[8] = {a0.x,a0.y,a0.z,a0.w,a1.x,a1.y,a1.z,a1.w};
                #pragma unroll
                for (int r = 0; r < 8; r++) {
                    unsigned long long ad = pack2(ar[r], ar[r]);
                    #pragma unroll
                    for (int cp = 0; cp < 4; cp++)
                        fma2(acc2[r][cp], ad, bp[cp]);
                }
            }

            // Unpack, then score = fl(fl(r2 - fl(2*e)) + c2) -- unchanged.
            const int kg0 = ch*KC + tx*8;
            float cn[8];
            #pragma unroll
            for (int c = 0; c < 8; c++) cn[c] = __ldg(cnq + kg0 + c);

            #pragma unroll
            for (int r = 0; r < 8; r++) {
                float accr[8];
                #pragma unroll
                for (int cp = 0; cp < 4; cp++)
                    unpack2(accr[2*cp], accr[2*cp+1], acc2[r][cp]);
                float r2v = r2_s[ty*8 + r];           // broadcast LDS
                #pragma unroll
                for (int c = 0; c < 8; c++) {
                    float e2 = __fmul_rn(2.0f, accr[c]);   // exact
                    float u  = __fsub_rn(r2v, e2);
                    float s  = __fadd_rn(u, cn[c]);
                    unsigned uu = __float_as_uint(s);
                    uu = (uu & 0x80000000u) ? ~uu : (uu | 0x80000000u);
                    unsigned long long key =
                        ((unsigned long long)uu << 32) | (unsigned)(kg0 + c);
                    if (key < best[r]) best[r] = key;   // ties -> lowest index
                }
            }
        }

        // Reduce over the 16 tx lanes (butterfly within half-warp)
        #pragma unroll
        for (int r = 0; r < 8; r++) {
            unsigned long long kmin = best[r];
            #pragma unroll
            for (int off = 8; off > 0; off >>= 1) {
                unsigned long long o = __shfl_xor_sync(0xffffffffu, kmin, off);
                if (o < kmin) kmin = o;
            }
            if (tx == 0) idx_s[ty*8 + r] = (int)(kmin & 0xFFFFFFFFull);
        }
        __syncthreads();   // idx visible; all GEMM reads of rs/r2 done

        // Residual update (one thread per token, d ascending) + next r2 with
        // the validated association + loss. UNCHANGED.
        if (tid < TM) {
            const int tok = tid;
            const int widx = idx_s[tok];
            const float4* crow =
                (const float4*)(cb + ((size_t)q * KK + widx) * DD);
            float a0[4] = {0.f,0.f,0.f,0.f}, a1[4] = {0.f,0.f,0.f,0.f};
            float lsum = 0.0f;
            #pragma unroll
            for (int j = 0; j < 16; j++) {
                float4 cA = __ldg(crow + 2*j);
                float4 cB = __ldg(crow + 2*j + 1);
                int d = 8*j;
                float n0 = __fsub_rn(rs[(d+0)*TM + tok], cA.x);
                float n1 = __fsub_rn(rs[(d+1)*TM + tok], cA.y);
                float n2 = __fsub_rn(rs[(d+2)*TM + tok], cA.z);
                float n3 = __fsub_rn(rs[(d+3)*TM + tok], cA.w);
                float n4 = __fsub_rn(rs[(d+4)*TM + tok], cB.x);
                float n5 = __fsub_rn(rs[(d+5)*TM + tok], cB.y);
                float n6 = __fsub_rn(rs[(d+6)*TM + tok], cB.z);
                float n7 = __fsub_rn(rs[(d+7)*TM + tok], cB.w);
                rs[(d+0)*TM + tok] = n0;
                rs[(d+1)*TM + tok] = n1;
                rs[(d+2)*TM + tok] = n2;
                rs[(d+3)*TM + tok] = n3;
                rs[(d+4)*TM + tok] = n4;
                rs[(d+5)*TM + tok] = n5;
                rs[(d+6)*TM + tok] = n6;
                rs[(d+7)*TM + tok] = n7;
                RED_ACC(a0, a1, n0, n1, n2, n3, n4, n5, n6, n7);
                lsum += n0*n0 + n1*n1 + n2*n2 + n3*n3
                      + n4*n4 + n5*n5 + n6*n6 + n7*n7;
            }
            r2_s[tok] = red_combine(a0, a1);
            lossAcc += (double)lsum;
        }
        // next iteration's leading __syncthreads orders rs/r2 writes
    }
    __syncthreads();

    // quantized = x - r_final (telescoped), layout [B,D,T]
    for (int i = tid; i < DD*TM/4; i += NT) {
        int tok4 = i & 31, d = i >> 5;
        float4 xv = __ldg((const float4*)(xb + (size_t)d * TT) + tok4);
        float4 rv = rs4[d * (TM/4) + tok4];
        float4 o;
        o.x = xv.x - rv.x; o.y = xv.y - rv.y;
        o.z = xv.z - rv.z; o.w = xv.w - rv.w;
        ((float4*)(out + ((size_t)b * DD + d) * TT + t0))[tok4] = o;
    }

    // total_loss = sum_q mean(r_{q+1}^2)
    if (write_loss) {
        #pragma unroll
        for (int off = 16; off > 0; off >>= 1)
            lossAcc += __shfl_xor_sync(0xffffffffu, lossAcc, off);
        if ((tid & 31) == 0) red[tid >> 5] = lossAcc;
        __syncthreads();
        if (tid == 0) {
            double s = 0.0;
            #pragma unroll
            for (int w = 0; w < 8; w++) s += red[w];
            atomicAdd(out + OUT_ELEMS, (float)(s * (1.0 / (double)OUT_ELEMS)));
        }
    }
}

// ---------------------------------------------------------------------------
extern "C" void kernel_launch(void* const* d_in, const int* in_sizes, int n_in,
                              void* d_out, int out_size)
{
    const float* x  = (const float*)d_in[0];   // [16,128,2048] fp32
    const float* cb = (const float*)d_in[1];   // [30,1024,128] fp32
    float* out = (float*)d_out;                // [16,128,2048] + loss scalar
    int write_loss = (out_size > OUT_ELEMS) ? 1 : 0;

    rvq_prep_kernel<<<(QQ*KK)/8, 256>>>(cb, out, write_loss);
    rvq_norm_kernel<<<(QQ*KK + 255)/256, 256>>>(cb);

    size_t smem = (size_t)(DD*TM + DD*KC + TM) * sizeof(float)
                + (size_t)TM * sizeof(int)
                + 8 * sizeof(double);
    cudaFuncSetAttribute(rvq_kernel,
                         cudaFuncAttributeMaxDynamicSharedMemorySize, (int)smem);
    rvq_kernel<<<NTOK/TM, NT, smem>>>(x, cb, out, write_loss);
}

// round 10
// speedup vs baseline: 1.3927x; 1.3927x over previous
#include <cuda_runtime.h>

// Problem constants
#define QQ 30
#define KK 1024
#define DD 128
#define BB 16
#define TT 2048
#define NTOK (BB*TT)          // 32768 tokens
#define OUT_ELEMS (NTOK*DD)   // 4194304 quantized elements

// Tiling
#define TM 128                // tokens per CTA
#define KC 128                // codes per chunk
#define NCH (KK/KC)           // 8 chunks
#define NT 256                // threads per CTA
#define KPW 68                // padded bf16 row: 64 data words + 4 pad (bank-safe)
#define CAP 4096              // candidate list capacity

// Scratch (no cudaMalloc): code norms, bf16 codebook (padded rows), per-q max c2
__device__ float    g_cn[QQ*KK];
__device__ unsigned g_cb16[(size_t)QQ*KK*KPW];   // 8.36 MB
__device__ unsigned g_cmax[QQ];

// ---------------------------------------------------------------------------
// Reference-exact square-sum reduce (validated bit-exact -- DO NOT TOUCH)
// ---------------------------------------------------------------------------
#define RED_ACC(a0, a1, v0, v1, v2, v3, v4, v5, v6, v7)                  \
    do {                                                                 \
        a0[0] = __fmaf_rn((v0), (v0), a0[0]);                            \
        a0[1] = __fmaf_rn((v1), (v1), a0[1]);                            \
        a0[2] = __fmaf_rn((v2), (v2), a0[2]);                            \
        a0[3] = __fmaf_rn((v3), (v3), a0[3]);                            \
        a1[0] = __fmaf_rn((v4), (v4), a1[0]);                            \
        a1[1] = __fmaf_rn((v5), (v5), a1[1]);                            \
        a1[2] = __fmaf_rn((v6), (v6), a1[2]);                            \
        a1[3] = __fmaf_rn((v7), (v7), a1[3]);                            \
    } while (0)

__device__ __forceinline__ float red_combine(const float a0[4], const float a1[4])
{
    float v0 = __fadd_rn(a0[0], a1[0]);
    float v1 = __fadd_rn(a0[1], a1[1]);
    float v2 = __fadd_rn(a0[2], a1[2]);
    float v3 = __fadd_rn(a0[3], a1[3]);
    return __fadd_rn(__fadd_rn(__fadd_rn(v0, v1), v2), v3);
}

// bf16x2 pack: low half = lo, high half = hi (cvt d, a(hi), b(lo))
__device__ __forceinline__ unsigned bf16pack(float lo, float hi)
{
    unsigned r;
    asm("cvt.rn.bf16x2.f32 %0, %1, %2;" : "=r"(r) : "f"(hi), "f"(lo));
    return r;
}

__device__ __forceinline__ void mma_bf16(float& c0, float& c1, float& c2, float& c3,
                                         unsigned a0, unsigned a1, unsigned a2, unsigned a3,
                                         unsigned b0, unsigned b1)
{
    asm("mma.sync.aligned.m16n8k16.row.col.f32.bf16.bf16.f32 "
        "{%0,%1,%2,%3}, {%4,%5,%6,%7}, {%8,%9}, {%0,%1,%2,%3};"
        : "+f"(c0), "+f"(c1), "+f"(c2), "+f"(c3)
        : "r"(a0), "r"(a1), "r"(a2), "r"(a3), "r"(b0), "r"(b1));
}

// Validated exact score key for (tok,k): chain ascending d, strict combine.
__device__ __forceinline__ unsigned long long exact_key(
    const float* rs, const float* cb, const float* cn, float r2v,
    int q, int tok, int k)
{
    const float4* crow = (const float4*)(cb + ((size_t)q * KK + k) * DD);
    float acc = 0.0f;
    #pragma unroll 8
    for (int j = 0; j < DD/4; j++) {
        float4 c4 = __ldg(crow + j);
        int d = j * 4;
        acc = __fmaf_rn(rs[(d+0)*TM + tok], c4.x, acc);
        acc = __fmaf_rn(rs[(d+1)*TM + tok], c4.y, acc);
        acc = __fmaf_rn(rs[(d+2)*TM + tok], c4.z, acc);
        acc = __fmaf_rn(rs[(d+3)*TM + tok], c4.w, acc);
    }
    float e2 = __fmul_rn(2.0f, acc);
    float u  = __fsub_rn(r2v, e2);
    float s  = __fadd_rn(u, cn[k]);
    unsigned uu = __float_as_uint(s);
    uu = (uu & 0x80000000u) ? ~uu : (uu | 0x80000000u);
    return ((unsigned long long)uu << 32) | (unsigned)k;
}

// ---------------------------------------------------------------------------
// Prep 0: zero loss slot + per-q cmax accumulators.
// ---------------------------------------------------------------------------
__global__ void rvq_prep0_kernel(float* __restrict__ out, int write_loss)
{
    if (write_loss && threadIdx.x == 0) out[OUT_ELEMS] = 0.0f;
    if (threadIdx.x < QQ) g_cmax[threadIdx.x] = 0u;
}

// ---------------------------------------------------------------------------
// Prep B: per code row: c2 (validated chain), bf16 packed row, cmax.
// ---------------------------------------------------------------------------
__global__ void rvq_norm_kernel(const float* __restrict__ cb)
{
    int gw = blockIdx.x * blockDim.x + threadIdx.x;   // code row (q*KK+k)
    if (gw >= QQ * KK) return;
    const float4* row = ((const float4*)cb) + (size_t)gw * (DD/4);
    unsigned* dst = g_cb16 + (size_t)gw * KPW;
    float a0[4] = {0.f,0.f,0.f,0.f}, a1[4] = {0.f,0.f,0.f,0.f};
    #pragma unroll
    for (int j = 0; j < 16; j++) {
        float4 A = __ldg(row + 2*j);
        float4 B = __ldg(row + 2*j + 1);
        RED_ACC(a0, a1, A.x, A.y, A.z, A.w, B.x, B.y, B.z, B.w);
        dst[4*j+0] = bf16pack(A.x, A.y);
        dst[4*j+1] = bf16pack(A.z, A.w);
        dst[4*j+2] = bf16pack(B.x, B.y);
        dst[4*j+3] = bf16pack(B.z, B.w);
    }
    dst[64] = dst[65] = dst[66] = dst[67] = 0u;
    float c2 = red_combine(a0, a1);
    g_cn[gw] = c2;
    atomicMax(&g_cmax[gw >> 10], __float_as_uint(c2));   // c2 > 0
}

// ---------------------------------------------------------------------------
// Main kernel: bf16 mma filter + exact rescore, validated update path.
// ---------------------------------------------------------------------------
__global__ __launch_bounds__(NT, 1)
void rvq_kernel(const float* __restrict__ x,
                const float* __restrict__ cb,
                float* __restrict__ out, int write_loss)
{
    extern __shared__ char smraw[];
    unsigned long long* bestkey = (unsigned long long*)smraw;     // [128]
    unsigned long long* cand    = bestkey + TM;                   // [CAP]
    double*   red  = (double*)(cand + CAP);                       // [8]
    float*    rs   = (float*)(red + 8);                           // [DD*TM]
    unsigned* rs16 = (unsigned*)(rs + DD*TM);                     // [TM*KPW]
    unsigned* cs16 = rs16 + TM*KPW;                               // [KC*KPW]
    float*    c2s  = (float*)(cs16 + KC*KPW);                     // [KC]
    float*    r2_s = c2s + KC;                                    // [TM]
    float*    smin = r2_s + TM;                                   // [TM]
    int*      cnts = (int*)(smin + TM);                           // [4]

    const int tid  = threadIdx.x;
    const int lane = tid & 31;
    const int g    = lane >> 2;      // mma group id (0..7)
    const int tig  = lane & 3;       // thread in group
    const int tw   = (tid >> 5) * 16; // warp token base

    const int blk = blockIdx.x;
    const int b   = blk >> 4;
    const int t0  = (blk & 15) * TM;
    const float* xb = x + (size_t)b * DD * TT + t0;
    float4* rs4 = (float4*)rs;

    // Load initial residual r0 = x (transposed [d][token])
    for (int i = tid; i < DD*TM/4; i += NT) {
        int tok4 = i & 31, d = i >> 5;
        float4 v = __ldg((const float4*)(xb + (size_t)d * TT) + tok4);
        rs4[d * (TM/4) + tok4] = v;
    }
    __syncthreads();

    // Initial r2 (validated association)
    if (tid < TM) {
        float a0[4] = {0.f,0.f,0.f,0.f}, a1[4] = {0.f,0.f,0.f,0.f};
        #pragma unroll
        for (int j = 0; j < 16; j++) {
            int d = 8*j;
            RED_ACC(a0, a1,
                    rs[(d+0)*TM + tid], rs[(d+1)*TM + tid],
                    rs[(d+2)*TM + tid], rs[(d+3)*TM + tid],
                    rs[(d+4)*TM + tid], rs[(d+5)*TM + tid],
                    rs[(d+6)*TM + tid], rs[(d+7)*TM + tid]);
        }
        r2_s[tid] = red_combine(a0, a1);
    }

    double lossAcc = 0.0;

    for (int q = 0; q < QQ; q++) {
        // Stage init + bf16 residual build (same-thread dep on rs: no pre-sync)
        if (tid < TM) {
            bestkey[tid] = 0xFFFFFFFFFFFFFFFFull;
            int t = tid;
            #pragma unroll
            for (int j = 0; j < 64; j++)
                rs16[t*KPW + j] = bf16pack(rs[(2*j)*TM + t], rs[(2*j+1)*TM + t]);
            rs16[t*KPW+64] = rs16[t*KPW+65] = rs16[t*KPW+66] = rs16[t*KPW+67] = 0u;
        }
        if (tid == 0) cnts[0] = 0;
        __syncthreads();

        // A fragments for this warp's 16 tokens, all 8 k-tiles (held in regs)
        unsigned af[8][4];
        #pragma unroll
        for (int kt = 0; kt < 8; kt++) {
            int base = (tw + g)*KPW + kt*8 + tig;
            af[kt][0] = rs16[base];
            af[kt][1] = rs16[base + 8*KPW];
            af[kt][2] = rs16[base + 4];
            af[kt][3] = rs16[base + 8*KPW + 4];
        }

        const float cmax = __uint_as_float(g_cmax[q]);
        const int tlo = tw + g, thi = tw + 8 + g;
        const float wlo = __fmaf_rn(0.05f, sqrtf(r2_s[tlo]*cmax), 1.0f);
        const float whi = __fmaf_rn(0.05f, sqrtf(r2_s[thi]*cmax), 1.0f);
        float mlo = 3.4e38f, mhi = 3.4e38f;

        const float* cnq = g_cn + q * KK;

        for (int ch = 0; ch < NCH; ch++) {
            __syncthreads();
            // stage bf16 code chunk + c2
            const unsigned* src = g_cb16 + ((size_t)q*KK + ch*KC) * KPW;
            for (int i = tid; i < KC*KPW; i += NT) cs16[i] = src[i];
            if (tid < KC) c2s[tid] = cnq[ch*KC + tid];
            __syncthreads();

            #pragma unroll 2
            for (int nt = 0; nt < 16; nt++) {
                float c0 = 0.f, c1 = 0.f, c2v = 0.f, c3 = 0.f;
                int bbase = (nt*8 + g)*KPW + tig;
                #pragma unroll
                for (int kt = 0; kt < 8; kt++) {
                    unsigned b0 = cs16[bbase + kt*8];
                    unsigned b1 = cs16[bbase + kt*8 + 4];
                    mma_bf16(c0, c1, c2v, c3,
                             af[kt][0], af[kt][1], af[kt][2], af[kt][3], b0, b1);
                }
                float cc0 = c2s[nt*8 + 2*tig], cc1 = c2s[nt*8 + 2*tig + 1];
                float s0 = cc0 - 2.f*c0,  s1 = cc1 - 2.f*c1;   // token tlo
                float s2 = cc0 - 2.f*c2v, s3 = cc1 - 2.f*c3;   // token thi
                mlo = fminf(mlo, fminf(s0, s1));
                mhi = fminf(mhi, fminf(s2, s3));
                // quad-share running min (tokens owned by 4 consecutive lanes)
                mlo = fminf(mlo, __shfl_xor_sync(0xffffffffu, mlo, 1));
                mlo = fminf(mlo, __shfl_xor_sync(0xffffffffu, mlo, 2));
                mhi = fminf(mhi, __shfl_xor_sync(0xffffffffu, mhi, 1));
                mhi = fminf(mhi, __shfl_xor_sync(0xffffffffu, mhi, 2));
                int code0 = ch*KC + nt*8 + 2*tig;
                float tl = mlo + wlo, th = mhi + whi;
                if (s0 <= tl || s1 <= tl || s2 <= th || s3 <= th) {
                    if (s0 <= tl) { int p = atomicAdd(cnts, 1); if (p < CAP)
                        cand[p] = ((unsigned long long)__float_as_uint(s0) << 32)
                                | (unsigned)((tlo << 10) | code0); }
                    if (s1 <= tl) { int p = atomicAdd(cnts, 1); if (p < CAP)
                        cand[p] = ((unsigned long long)__float_as_uint(s1) << 32)
                                | (unsigned)((tlo << 10) | (code0 + 1)); }
                    if (s2 <= th) { int p = atomicAdd(cnts, 1); if (p < CAP)
                        cand[p] = ((unsigned long long)__float_as_uint(s2) << 32)
                                | (unsigned)((thi << 10) | code0); }
                    if (s3 <= th) { int p = atomicAdd(cnts, 1); if (p < CAP)
                        cand[p] = ((unsigned long long)__float_as_uint(s3) << 32)
                                | (unsigned)((thi << 10) | (code0 + 1)); }
                }
            }
        }

        // Final per-token approx minima
        if (tig == 0) { smin[tlo] = mlo; smin[thi] = mhi; }
        __syncthreads();

        int cnt = cnts[0];
        if (cnt <= CAP) {
            // exact rescore of surviving candidates (validated chain)
            for (int i = tid; i < cnt; i += NT) {
                unsigned long long e = cand[i];
                float sv = __uint_as_float((unsigned)(e >> 32));
                unsigned tc = (unsigned)e;
                int tok = (tc >> 10) & 127, k = tc & 1023;
                float Wt = __fmaf_rn(0.05f, sqrtf(r2_s[tok]*cmax), 1.0f);
                if (sv <= smin[tok] + Wt) {
                    unsigned long long key =
                        exact_key(rs, cb, cnq, r2_s[tok], q, tok, k);
                    atomicMin(&bestkey[tok], key);
                }
            }
        } else {
            // overflow fallback: exact full scan (deterministic, ~never)
            if (tid < TM) {
                unsigned long long bk = 0xFFFFFFFFFFFFFFFFull;
                for (int k = 0; k < KK; k++) {
                    unsigned long long key =
                        exact_key(rs, cb, cnq, r2_s[tid], q, tid, k);
                    if (key < bk) bk = key;
                }
                bestkey[tid] = bk;
            }
        }
        __syncthreads();

        // Residual update + next r2 (validated path, UNCHANGED)
        if (tid < TM) {
            const int tok = tid;
            const int widx = (int)(bestkey[tok] & 0xFFFFFFFFull);
            const float4* crow =
                (const float4*)(cb + ((size_t)q * KK + widx) * DD);
            float a0[4] = {0.f,0.f,0.f,0.f}, a1[4] = {0.f,0.f,0.f,0.f};
            float lsum = 0.0f;
            #pragma unroll
            for (int j = 0; j < 16; j++) {
                float4 cA = __ldg(crow + 2*j);
                float4 cB = __ldg(crow + 2*j + 1);
                int d = 8*j;
                float n0 = __fsub_rn(rs[(d+0)*TM + tok], cA.x);
                float n1 = __fsub_rn(rs[(d+1)*TM + tok], cA.y);
                float n2 = __fsub_rn(rs[(d+2)*TM + tok], cA.z);
                float n3 = __fsub_rn(rs[(d+3)*TM + tok], cA.w);
                float n4 = __fsub_rn(rs[(d+4)*TM + tok], cB.x);
                float n5 = __fsub_rn(rs[(d+5)*TM + tok], cB.y);
                float n6 = __fsub_rn(rs[(d+6)*TM + tok], cB.z);
                float n7 = __fsub_rn(rs[(d+7)*TM + tok], cB.w);
                rs[(d+0)*TM + tok] = n0;
                rs[(d+1)*TM + tok] = n1;
                rs[(d+2)*TM + tok] = n2;
                rs[(d+3)*TM + tok] = n3;
                rs[(d+4)*TM + tok] = n4;
                rs[(d+5)*TM + tok] = n5;
                rs[(d+6)*TM + tok] = n6;
                rs[(d+7)*TM + tok] = n7;
                RED_ACC(a0, a1, n0, n1, n2, n3, n4, n5, n6, n7);
                lsum += n0*n0 + n1*n1 + n2*n2 + n3*n3
                      + n4*n4 + n5*n5 + n6*n6 + n7*n7;
            }
            r2_s[tok] = red_combine(a0, a1);
            lossAcc += (double)lsum;
        }
        // next stage's post-build __syncthreads orders rs/r2 writes
    }
    __syncthreads();

    // quantized = x - r_final (telescoped), layout [B,D,T]
    for (int i = tid; i < DD*TM/4; i += NT) {
        int tok4 = i & 31, d = i >> 5;
        float4 xv = __ldg((const float4*)(xb + (size_t)d * TT) + tok4);
        float4 rv = rs4[d * (TM/4) + tok4];
        float4 o;
        o.x = xv.x - rv.x; o.y = xv.y - rv.y;
        o.z = xv.z - rv.z; o.w = xv.w - rv.w;
        ((float4*)(out + ((size_t)b * DD + d) * TT + t0))[tok4] = o;
    }

    // total_loss = sum_q mean(r_{q+1}^2)
    if (write_loss) {
        #pragma unroll
        for (int off = 16; off > 0; off >>= 1)
            lossAcc += __shfl_xor_sync(0xffffffffu, lossAcc, off);
        if ((tid & 31) == 0) red[tid >> 5] = lossAcc;
        __syncthreads();
        if (tid == 0) {
            double s = 0.0;
            #pragma unroll
            for (int w = 0; w < 8; w++) s += red[w];
            atomicAdd(out + OUT_ELEMS, (float)(s * (1.0 / (double)OUT_ELEMS)));
        }
    }
}

// ---------------------------------------------------------------------------
extern "C" void kernel_launch(void* const* d_in, const int* in_sizes, int n_in,
                              void* d_out, int out_size)
{
    const float* x  = (const float*)d_in[0];   // [16,128,2048] fp32
    const float* cb = (const float*)d_in[1];   // [30,1024,128] fp32
    float* out = (float*)d_out;                // [16,128,2048] + loss scalar
    int write_loss = (out_size > OUT_ELEMS) ? 1 : 0;

    rvq_prep0_kernel<<<1, 64>>>(out, write_loss);
    rvq_norm_kernel<<<(QQ*KK + 255)/256, 256>>>(cb);

    size_t smem = (size_t)TM * 8            // bestkey
                + (size_t)CAP * 8           // cand
                + 8 * 8                     // red
                + (size_t)DD*TM * 4         // rs
                + (size_t)TM*KPW * 4        // rs16
                + (size_t)KC*KPW * 4        // cs16
                + (size_t)KC * 4            // c2s
                + (size_t)TM * 4            // r2_s
                + (size_t)TM * 4            // smin
                + 16;                       // cnts
    cudaFuncSetAttribute(rvq_kernel,
                         cudaFuncAttributeMaxDynamicSharedMemorySize, (int)smem);
    rvq_kernel<<<NTOK/TM, NT, smem>>>(x, cb, out, write_loss);
}

// round 12
// speedup vs baseline: 2.4380x; 1.7506x over previous
#include <cuda_runtime.h>
#include <cstdint>

// Problem constants
#define QQ 30
#define KK 1024
#define DD 128
#define BB 16
#define TT 2048
#define NTOK (BB*TT)          // 32768 tokens
#define OUT_ELEMS (NTOK*DD)   // 4194304 quantized elements

// Tiling
#define TM 128                // tokens per CTA
#define KC 128                // codes per chunk
#define NCH 8                 // chunks per stage
#define NT 256                // threads per CTA
#define KPW 68                // padded bf16 row: 64 data words + 4 pad
#define CAP 4096              // candidate list capacity (per CTA, in gmem)
#define NBLK (NTOK/TM)        // 256 CTAs

// Scratch (no cudaMalloc): code norms, bf16 codebook (padded rows), per-q max
// c2, per-CTA candidate lists.
__device__ float    g_cn[QQ*KK];
__device__ unsigned g_cb16[(size_t)QQ*KK*KPW];           // 8.36 MB
__device__ unsigned g_cmax[QQ];
__device__ unsigned long long g_cand[(size_t)NBLK*CAP];  // 8 MB

// SMEM layout (bytes): total 103,040 -> 2 CTAs/SM
#define SM_BEST 0          // 128 u64
#define SM_RED  1024       // 8 doubles
#define SM_R2   1088       // 128 f
#define SM_SMIN 1600       // 128 f
#define SM_C2   2112       // 128 f
#define SM_CNT  2624       // int
#define SM_RS   2688       // 128*128 f = 65536
#define SM_CS   68224      // 128*68*4 = 34816
#define SM_TOTAL 103040

// ---------------------------------------------------------------------------
// Reference-exact square-sum reduce (validated bit-exact -- DO NOT TOUCH)
// ---------------------------------------------------------------------------
#define RED_ACC(a0, a1, v0, v1, v2, v3, v4, v5, v6, v7)                  \
    do {                                                                 \
        a0[0] = __fmaf_rn((v0), (v0), a0[0]);                            \
        a0[1] = __fmaf_rn((v1), (v1), a0[1]);                            \
        a0[2] = __fmaf_rn((v2), (v2), a0[2]);                            \
        a0[3] = __fmaf_rn((v3), (v3), a0[3]);                            \
        a1[0] = __fmaf_rn((v4), (v4), a1[0]);                            \
        a1[1] = __fmaf_rn((v5), (v5), a1[1]);                            \
        a1[2] = __fmaf_rn((v6), (v6), a1[2]);                            \
        a1[3] = __fmaf_rn((v7), (v7), a1[3]);                            \
    } while (0)

static __device__ __forceinline__ float red_combine(const float a0[4], const float a1[4])
{
    float v0 = __fadd_rn(a0[0], a1[0]);
    float v1 = __fadd_rn(a0[1], a1[1]);
    float v2 = __fadd_rn(a0[2], a1[2]);
    float v3 = __fadd_rn(a0[3], a1[3]);
    return __fadd_rn(__fadd_rn(__fadd_rn(v0, v1), v2), v3);
}

// bf16x2 pack: low half = lo, high half = hi
static __device__ __forceinline__ unsigned bf16pack(float lo, float hi)
{
    unsigned r;
    asm("cvt.rn.bf16x2.f32 %0, %1, %2;" : "=r"(r) : "f"(hi), "f"(lo));
    return r;
}

static __device__ __forceinline__ unsigned smem_u32(const void* p)
{
    unsigned a;
    asm("{ .reg .u64 t; cvta.to.shared.u64 t, %1; cvt.u32.u64 %0, t; }"
        : "=r"(a) : "l"(p));
    return a;
}

static __device__ __forceinline__ void mma_bf16(float& c0, float& c1, float& c2, float& c3,
                                                unsigned a0, unsigned a1, unsigned a2, unsigned a3,
                                                unsigned b0, unsigned b1)
{
    asm("mma.sync.aligned.m16n8k16.row.col.f32.bf16.bf16.f32 "
        "{%0,%1,%2,%3}, {%4,%5,%6,%7}, {%8,%9}, {%0,%1,%2,%3};"
        : "+f"(c0), "+f"(c1), "+f"(c2), "+f"(c3)
        : "r"(a0), "r"(a1), "r"(a2), "r"(a3), "r"(b0), "r"(b1));
}

static __device__ __forceinline__ void ldm4(unsigned* r, unsigned addr)
{
    asm volatile("ldmatrix.sync.aligned.m8n8.x4.shared.b16 {%0,%1,%2,%3}, [%4];"
                 : "=r"(r[0]), "=r"(r[1]), "=r"(r[2]), "=r"(r[3]) : "r"(addr));
}

// Validated exact score key for (tok,k): chain ascending d, strict combine.
static __device__ __forceinline__ unsigned long long exact_key(
    const float* rs, const float* cb, const float* cn, float r2v,
    int q, int tok, int k)
{
    const float4* crow = (const float4*)(cb + ((size_t)q * KK + k) * DD);
    float acc = 0.0f;
    #pragma unroll 8
    for (int j = 0; j < DD/4; j++) {
        float4 c4 = __ldg(crow + j);
        int d = j * 4;
        acc = __fmaf_rn(rs[(d+0)*TM + tok], c4.x, acc);
        acc = __fmaf_rn(rs[(d+1)*TM + tok], c4.y, acc);
        acc = __fmaf_rn(rs[(d+2)*TM + tok], c4.z, acc);
        acc = __fmaf_rn(rs[(d+3)*TM + tok], c4.w, acc);
    }
    float e2 = __fmul_rn(2.0f, acc);
    float u  = __fsub_rn(r2v, e2);
    float s  = __fadd_rn(u, cn[k]);
    unsigned uu = __float_as_uint(s);
    uu = (uu & 0x80000000u) ? ~uu : (uu | 0x80000000u);
    return ((unsigned long long)uu << 32) | (unsigned)k;
}

// ---------------------------------------------------------------------------
// Prep 0: zero loss slot + cmax accumulators.
// ---------------------------------------------------------------------------
__global__ void rvq_prep0_kernel(float* __restrict__ out, int write_loss)
{
    if (write_loss && threadIdx.x == 0) out[OUT_ELEMS] = 0.0f;
    if (threadIdx.x < QQ) g_cmax[threadIdx.x] = 0u;
}

// ---------------------------------------------------------------------------
// Prep B: per code row: c2 (validated chain), bf16 packed row, cmax.
// ---------------------------------------------------------------------------
__global__ void rvq_norm_kernel(const float* __restrict__ cb)
{
    int gw = blockIdx.x * blockDim.x + threadIdx.x;   // code row (q*KK+k)
    if (gw >= QQ * KK) return;
    const float4* row = ((const float4*)cb) + (size_t)gw * (DD/4);
    unsigned* dst = g_cb16 + (size_t)gw * KPW;
    float a0[4] = {0.f,0.f,0.f,0.f}, a1[4] = {0.f,0.f,0.f,0.f};
    #pragma unroll
    for (int j = 0; j < 16; j++) {
        float4 A = __ldg(row + 2*j);
        float4 B = __ldg(row + 2*j + 1);
        RED_ACC(a0, a1, A.x, A.y, A.z, A.w, B.x, B.y, B.z, B.w);
        dst[4*j+0] = bf16pack(A.x, A.y);
        dst[4*j+1] = bf16pack(A.z, A.w);
        dst[4*j+2] = bf16pack(B.x, B.y);
        dst[4*j+3] = bf16pack(B.z, B.w);
    }
    dst[64] = dst[65] = dst[66] = dst[67] = 0u;
    float c2 = red_combine(a0, a1);
    g_cn[gw] = c2;
    atomicMax(&g_cmax[gw >> 10], __float_as_uint(c2));   // c2 > 0
}

// ---------------------------------------------------------------------------
// Main kernel: bf16 HMMA filter (ldmatrix B frags, reg-built A frags,
// 2 CTAs/SM) + validated exact rescore / update / r2 / loss.
// ---------------------------------------------------------------------------
__global__ __launch_bounds__(NT, 2)
void rvq_kernel(const float* __restrict__ x,
                const float* __restrict__ cb,
                float* __restrict__ out, int write_loss)
{
    extern __shared__ char sm[];
    unsigned long long* bestkey = (unsigned long long*)(sm + SM_BEST);
    double*   red  = (double*)(sm + SM_RED);
    float*    r2_s = (float*)(sm + SM_R2);
    float*    smin = (float*)(sm + SM_SMIN);
    float*    c2s  = (float*)(sm + SM_C2);
    int*      cnts = (int*)(sm + SM_CNT);
    float*    rs   = (float*)(sm + SM_RS);
    float4*   rs4  = (float4*)rs;
    const unsigned csb = smem_u32(sm + SM_CS);

    const int tid  = threadIdx.x;
    const int lane = tid & 31;
    const int g    = lane >> 2;       // mma group id (0..7)
    const int tig  = lane & 3;        // thread in group
    const int tw   = (tid >> 5) * 16; // warp token base
    const int lm_r = lane & 7;        // ldmatrix row
    const int lm_m = lane >> 3;       // ldmatrix matrix id

    const int blk = blockIdx.x;
    const int b   = blk >> 4;
    const int t0  = (blk & 15) * TM;
    const float* xb = x + (size_t)b * DD * TT + t0;
    unsigned long long* candg = g_cand + (size_t)blk * CAP;

    // Load initial residual r0 = x (transposed [d][token])
    for (int i = tid; i < DD*TM/4; i += NT) {
        int tok4 = i & 31, d = i >> 5;
        float4 v = __ldg((const float4*)(xb + (size_t)d * TT) + tok4);
        rs4[d * (TM/4) + tok4] = v;
    }
    __syncthreads();

    // Initial r2 (validated association)
    if (tid < TM) {
        float a0[4] = {0.f,0.f,0.f,0.f}, a1[4] = {0.f,0.f,0.f,0.f};
        #pragma unroll
        for (int j = 0; j < 16; j++) {
            int d = 8*j;
            RED_ACC(a0, a1,
                    rs[(d+0)*TM + tid], rs[(d+1)*TM + tid],
                    rs[(d+2)*TM + tid], rs[(d+3)*TM + tid],
                    rs[(d+4)*TM + tid], rs[(d+5)*TM + tid],
                    rs[(d+6)*TM + tid], rs[(d+7)*TM + tid]);
        }
        r2_s[tid] = red_combine(a0, a1);
    }
    __syncthreads();

    double lossAcc = 0.0;

    for (int q = 0; q < QQ; q++) {
        if (tid < TM) bestkey[tid] = 0xFFFFFFFFFFFFFFFFull;
        if (tid == 0) cnts[0] = 0;

        // Build A fragments straight from rs (per warp; tokens tlo/thi)
        const int tlo = tw + g, thi = tw + 8 + g;
        unsigned af[8][4];
        #pragma unroll
        for (int kt = 0; kt < 8; kt++) {
            int d0 = kt*16 + 2*tig;
            af[kt][0] = bf16pack(rs[(d0  )*TM + tlo], rs[(d0+1)*TM + tlo]);
            af[kt][1] = bf16pack(rs[(d0  )*TM + thi], rs[(d0+1)*TM + thi]);
            af[kt][2] = bf16pack(rs[(d0+8)*TM + tlo], rs[(d0+9)*TM + tlo]);
            af[kt][3] = bf16pack(rs[(d0+8)*TM + thi], rs[(d0+9)*TM + thi]);
        }

        const float cmax = __uint_as_float(g_cmax[q]);
        const float* cnq = g_cn + q * KK;
        const float wlo = __fmaf_rn(0.05f, sqrtf(r2_s[tlo] * cmax), 1.0f);
        const float whi = __fmaf_rn(0.05f, sqrtf(r2_s[thi] * cmax), 1.0f);
        float mlo = 3.4e38f, mhi = 3.4e38f;

        for (int ch = 0; ch < NCH; ch++) {
            __syncthreads();   // prev chunk's readers done (and q-init visible)
            // Stage bf16 code chunk (flat, pre-padded rows) + c2
            {
                const uint4* src = (const uint4*)(g_cb16 + ((size_t)(q*KK + ch*KC)) * KPW);
                uint4* dst = (uint4*)(sm + SM_CS);
                for (int i = tid; i < KC*KPW/4; i += NT) dst[i] = __ldg(src + i);
                if (tid < KC) c2s[tid] = cnq[ch*KC + tid];
            }
            __syncthreads();

            #pragma unroll 2
            for (int nt = 0; nt < 16; nt++) {
                // B fragments via 4x ldmatrix.x4 (same contents as validated
                // scalar loads: thread(g,tig) -> code row g, k-pairs 2tig)
                unsigned bf[16];
                unsigned rowb = csb + (unsigned)((nt*8 + lm_r) * (KPW*4) + lm_m*16);
                ldm4(bf + 0,  rowb);
                ldm4(bf + 4,  rowb + 64);
                ldm4(bf + 8,  rowb + 128);
                ldm4(bf + 12, rowb + 192);

                float c0 = 0.f, c1 = 0.f, c2v = 0.f, c3 = 0.f;
                #pragma unroll
                for (int kt = 0; kt < 8; kt++)
                    mma_bf16(c0, c1, c2v, c3,
                             af[kt][0], af[kt][1], af[kt][2], af[kt][3],
                             bf[2*kt], bf[2*kt+1]);

                float cc0 = c2s[nt*8 + 2*tig], cc1 = c2s[nt*8 + 2*tig + 1];
                float s0 = cc0 - 2.f*c0,  s1 = cc1 - 2.f*c1;   // token tlo
                float s2 = cc0 - 2.f*c2v, s3 = cc1 - 2.f*c3;   // token thi
                mlo = fminf(mlo, fminf(s0, s1));
                mhi = fminf(mhi, fminf(s2, s3));
                mlo = fminf(mlo, __shfl_xor_sync(0xffffffffu, mlo, 1));
                mlo = fminf(mlo, __shfl_xor_sync(0xffffffffu, mlo, 2));
                mhi = fminf(mhi, __shfl_xor_sync(0xffffffffu, mhi, 1));
                mhi = fminf(mhi, __shfl_xor_sync(0xffffffffu, mhi, 2));
                int code0 = ch*KC + nt*8 + 2*tig;
                float tl = mlo + wlo, th = mhi + whi;
                if (s0 <= tl || s1 <= tl || s2 <= th || s3 <= th) {
                    if (s0 <= tl) { int p = atomicAdd(cnts, 1); if (p < CAP)
                        candg[p] = ((unsigned long long)__float_as_uint(s0) << 32)
                                 | (unsigned)((tlo << 10) | code0); }
                    if (s1 <= tl) { int p = atomicAdd(cnts, 1); if (p < CAP)
                        candg[p] = ((unsigned long long)__float_as_uint(s1) << 32)
                                 | (unsigned)((tlo << 10) | (code0 + 1)); }
                    if (s2 <= th) { int p = atomicAdd(cnts, 1); if (p < CAP)
                        candg[p] = ((unsigned long long)__float_as_uint(s2) << 32)
                                 | (unsigned)((thi << 10) | code0); }
                    if (s3 <= th) { int p = atomicAdd(cnts, 1); if (p < CAP)
                        candg[p] = ((unsigned long long)__float_as_uint(s3) << 32)
                                 | (unsigned)((thi << 10) | (code0 + 1)); }
                }
            }
        }
        // Final per-token approx minima (tig 0 holds quad-merged value)
        if (tig == 0) { smin[tlo] = mlo; smin[thi] = mhi; }
        __syncthreads();

        int cnt = cnts[0];
        if (cnt <= CAP) {
            // Exact rescore of survivors (validated chain)
            for (int i = tid; i < cnt; i += NT) {
                unsigned long long e = candg[i];
                float sv = __uint_as_float((unsigned)(e >> 32));
                unsigned tc = (unsigned)e;
                int tok = (tc >> 10) & 127, k = tc & 1023;
                float Wk = __fmaf_rn(0.05f, sqrtf(r2_s[tok] * cmax), 1.0f);
                if (sv <= smin[tok] + Wk) {
                    unsigned long long key =
                        exact_key(rs, cb, cnq, r2_s[tok], q, tok, k);
                    atomicMin(&bestkey[tok], key);
                }
            }
        } else {
            // overflow fallback: exact full scan (deterministic, ~never)
            if (tid < TM) {
                unsigned long long bk = 0xFFFFFFFFFFFFFFFFull;
                for (int k = 0; k < KK; k++) {
                    unsigned long long key =
                        exact_key(rs, cb, cnq, r2_s[tid], q, tid, k);
                    if (key < bk) bk = key;
                }
                bestkey[tid] = bk;
            }
        }
        __syncthreads();

        // Residual update + next r2 (validated path, UNCHANGED)
        if (tid < TM) {
            const int tok = tid;
            const int widx = (int)(bestkey[tok] & 0xFFFFFFFFull);
            const float4* crow =
                (const float4*)(cb + ((size_t)q * KK + widx) * DD);
            float a0[4] = {0.f,0.f,0.f,0.f}, a1[4] = {0.f,0.f,0.f,0.f};
            float lsum = 0.0f;
            #pragma unroll
            for (int j = 0; j < 16; j++) {
                float4 cA = __ldg(crow + 2*j);
                float4 cB = __ldg(crow + 2*j + 1);
                int d = 8*j;
                float n0 = __fsub_rn(rs[(d+0)*TM + tok], cA.x);
                float n1 = __fsub_rn(rs[(d+1)*TM + tok], cA.y);
                float n2 = __fsub_rn(rs[(d+2)*TM + tok], cA.z);
                float n3 = __fsub_rn(rs[(d+3)*TM + tok], cA.w);
                float n4 = __fsub_rn(rs[(d+4)*TM + tok], cB.x);
                float n5 = __fsub_rn(rs[(d+5)*TM + tok], cB.y);
                float n6 = __fsub_rn(rs[(d+6)*TM + tok], cB.z);
                float n7 = __fsub_rn(rs[(d+7)*TM + tok], cB.w);
                rs[(d+0)*TM + tok] = n0;
                rs[(d+1)*TM + tok] = n1;
                rs[(d+2)*TM + tok] = n2;
                rs[(d+3)*TM + tok] = n3;
                rs[(d+4)*TM + tok] = n4;
                rs[(d+5)*TM + tok] = n5;
                rs[(d+6)*TM + tok] = n6;
                rs[(d+7)*TM + tok] = n7;
                RED_ACC(a0, a1, n0, n1, n2, n3, n4, n5, n6, n7);
                lsum += n0*n0 + n1*n1 + n2*n2 + n3*n3
                      + n4*n4 + n5*n5 + n6*n6 + n7*n7;
            }
            r2_s[tok] = red_combine(a0, a1);
            lossAcc += (double)lsum;
        }
        __syncthreads();   // rs/r2 visible before next stage's A-frag build
    }

    // quantized = x - r_final (telescoped), layout [B,D,T]
    for (int i = tid; i < DD*TM/4; i += NT) {
        int tok4 = i & 31, d = i >> 5;
        float4 xv = __ldg((const float4*)(xb + (size_t)d * TT) + tok4);
        float4 rv = rs4[d * (TM/4) + tok4];
        float4 o;
        o.x = xv.x - rv.x; o.y = xv.y - rv.y;
        o.z = xv.z - rv.z; o.w = xv.w - rv.w;
        ((float4*)(out + ((size_t)b * DD + d) * TT + t0))[tok4] = o;
    }

    // total_loss = sum_q mean(r_{q+1}^2)
    if (write_loss) {
        #pragma unroll
        for (int off = 16; off > 0; off >>= 1)
            lossAcc += __shfl_xor_sync(0xffffffffu, lossAcc, off);
        if ((tid & 31) == 0) red[tid >> 5] = lossAcc;
        __syncthreads();
        if (tid == 0) {
            double s = 0.0;
            #pragma unroll
            for (int w = 0; w < 8; w++) s += red[w];
            atomicAdd(out + OUT_ELEMS, (float)(s * (1.0 / (double)OUT_ELEMS)));
        }
    }
}

// ---------------------------------------------------------------------------
extern "C" void kernel_launch(void* const* d_in, const int* in_sizes, int n_in,
                              void* d_out, int out_size)
{
    const float* x  = (const float*)d_in[0];   // [16,128,2048] fp32
    const float* cb = (const float*)d_in[1];   // [30,1024,128] fp32
    float* out = (float*)d_out;                // [16,128,2048] + loss scalar
    int write_loss = (out_size > OUT_ELEMS) ? 1 : 0;

    rvq_prep0_kernel<<<1, 64>>>(out, write_loss);
    rvq_norm_kernel<<<(QQ*KK + 255)/256, 256>>>(cb);

    cudaFuncSetAttribute(rvq_kernel,
                         cudaFuncAttributeMaxDynamicSharedMemorySize, SM_TOTAL);
    rvq_kernel<<<NBLK, NT, SM_TOTAL>>>(x, cb, out, write_loss);
}